// round 16
// baseline (speedup 1.0000x reference)
#include <cuda_runtime.h>
#include <stdint.h>

// Problem constants
#define B_  4
#define N_  7
#define L_  512
#define S_  512
#define H_  8
#define E_  64
#define D_  64

constexpr int M_TILE  = 128;     // Q rows per CTA (4 warps x 32 rows)
constexpr int S_TILE  = 32;      // keys per iteration (keeps prefetch regs small)
constexpr int THREADS = 128;
constexpr int NSTEPS  = S_ / S_TILE;     // 16

// Q is pre-scaled by 0.125*log2(e) at staging -> QK^T emits log2-domain scores.
#define QSCALE 0.18033688f

// fp16 tiles, row stride 36 words (64 halves + 8 pad). 36 % 32 == 4 keeps all
// ldmatrix (normal and trans) phases and staging stores conflict-free.
constexpr int RSTRIDE   = 36;
constexpr int KV_WORDS  = S_TILE * RSTRIDE;          // 1152 words per K or V tile
constexpr int BUF_WORDS = 2 * KV_WORDS;              // K + V per buffer = 2304
constexpr int Q_OFFw    = 2 * BUF_WORDS;             // 4608
constexpr int SMEM_WORDS = Q_OFFw + M_TILE * RSTRIDE;    // 9216
constexpr int SMEM_BYTES = SMEM_WORDS * 4;               // 36864 B -> 2 CTAs/SM

__device__ __forceinline__ uint32_t smem_u32(const void* p) {
    uint32_t a;
    asm("{ .reg .u64 t; cvta.to.shared.u64 t, %1; cvt.u32.u64 %0, t; }" : "=r"(a) : "l"(p));
    return a;
}

// pack two f32 into f16x2 (lo = first element)
__device__ __forceinline__ uint32_t pack_h2(float lo, float hi) {
    uint32_t r;
    asm("cvt.rn.f16x2.f32 %0, %1, %2;" : "=r"(r) : "f"(hi), "f"(lo));
    return r;
}

__device__ __forceinline__ void ldm_x4(uint32_t* r, uint32_t addr) {
    asm volatile("ldmatrix.sync.aligned.m8n8.x4.shared.b16 {%0,%1,%2,%3}, [%4];"
                 : "=r"(r[0]), "=r"(r[1]), "=r"(r[2]), "=r"(r[3])
                 : "r"(addr));
}

__device__ __forceinline__ void ldm_x4_t(uint32_t* r, uint32_t addr) {
    asm volatile("ldmatrix.sync.aligned.m8n8.x4.trans.shared.b16 {%0,%1,%2,%3}, [%4];"
                 : "=r"(r[0]), "=r"(r[1]), "=r"(r[2]), "=r"(r[3])
                 : "r"(addr));
}

// D = A(16x16) * B(16x8) + D, f16 in, f32 accum (sm_80+ baseline PTX)
__device__ __forceinline__ void mma_f16(float* d, const uint32_t* a,
                                        uint32_t b0, uint32_t b1) {
    asm volatile(
        "mma.sync.aligned.m16n8k16.row.col.f32.f16.f16.f32 "
        "{%0,%1,%2,%3}, {%4,%5,%6,%7}, {%8,%9}, {%0,%1,%2,%3};"
        : "+f"(d[0]), "+f"(d[1]), "+f"(d[2]), "+f"(d[3])
        : "r"(a[0]), "r"(a[1]), "r"(a[2]), "r"(a[3]),
          "r"(b0), "r"(b1));
}

// 2^t on the FMA/ALU pipes (input already in log2 domain).
__device__ __forceinline__ float pexp2(float t) {
    float z = t + 12582912.0f;               // round-to-nearest magic
    int   n = __float_as_int(z) - 0x4B400000;
    float f = t - (z - 12582912.0f);         // f in [-0.5, 0.5]
    float p = 9.6181291e-3f;
    p = fmaf(p, f, 5.5504109e-2f);
    p = fmaf(p, f, 2.4022651e-1f);
    p = fmaf(p, f, 6.9314718e-1f);
    p = fmaf(p, f, 1.0f);
    return __int_as_float(__float_as_int(p) + (n << 23));
}

__global__ __launch_bounds__(THREADS, 2)
void attn_hmma_f16_kernel(const float* __restrict__ Qg,
                          const float* __restrict__ Kg,
                          const float* __restrict__ Vg,
                          float* __restrict__ Og) {
    extern __shared__ uint32_t sm[];
    const uint32_t sbase = smem_u32(sm);

    const int tid  = threadIdx.x;
    const int lane = tid & 31;
    const int w    = tid >> 5;       // warp 0..3 : Q rows w*32 .. w*32+31
    const int g    = lane >> 2;      // groupID
    const int t    = lane & 3;       // threadID-in-group

    const int l0 = blockIdx.x * M_TILE;
    const int bn = blockIdx.y >> 3;
    const int h  = blockIdx.y & 7;

    const float* Qh = Qg + bn * (L_ * H_ * E_) + h * E_;
    const float* Kh = Kg + bn * (S_ * H_ * E_) + h * E_;
    const float* Vh = Vg + bn * (S_ * H_ * D_) + h * D_;

    // ---- Stage Q tile 128x64 fp16, pre-scaled into log2 domain ----
    #pragma unroll
    for (int j = 0; j < 16; ++j) {
        const int idx = tid + j * THREADS;      // 0..2047
        const int r   = idx >> 4;               // 0..127
        const int c4  = (idx & 15) << 2;
        float4 v = *reinterpret_cast<const float4*>(Qh + (l0 + r) * 512 + c4);
        *reinterpret_cast<uint2*>(&sm[Q_OFFw + r * RSTRIDE + (c4 >> 1)])
            = make_uint2(pack_h2(v.x * QSCALE, v.y * QSCALE),
                         pack_h2(v.z * QSCALE, v.w * QSCALE));
    }
    // ---- Stage K/V tile 0 (both row-major, coalesced) into buffer 0 ----
    #pragma unroll
    for (int j = 0; j < 4; ++j) {
        const int idx = tid + j * THREADS;      // 0..511
        const int r   = idx >> 4;               // 0..31
        const int c4  = (idx & 15) << 2;
        float4 kv = *reinterpret_cast<const float4*>(Kh + r * 512 + c4);
        *reinterpret_cast<uint2*>(&sm[r * RSTRIDE + (c4 >> 1)])
            = make_uint2(pack_h2(kv.x, kv.y), pack_h2(kv.z, kv.w));
        float4 vv = *reinterpret_cast<const float4*>(Vh + r * 512 + c4);
        *reinterpret_cast<uint2*>(&sm[KV_WORDS + r * RSTRIDE + (c4 >> 1)])
            = make_uint2(pack_h2(vv.x, vv.y), pack_h2(vv.z, vv.w));
    }
    __syncthreads();

    // ---- Resident A fragments of Q: 2 mf blocks of 16 rows ----
    uint32_t Qa[2][4][4];
    #pragma unroll
    for (int mf = 0; mf < 2; ++mf) {
        const uint32_t* q0 = &sm[Q_OFFw + (w * 32 + mf * 16 + g) * RSTRIDE];
        const uint32_t* q1 = q0 + 8 * RSTRIDE;
        #pragma unroll
        for (int kc = 0; kc < 4; ++kc) {
            Qa[mf][kc][0] = q0[kc * 8 + t];
            Qa[mf][kc][1] = q1[kc * 8 + t];
            Qa[mf][kc][2] = q0[kc * 8 + t + 4];
            Qa[mf][kc][3] = q1[kc * 8 + t + 4];
        }
    }

    // lane-invariant ldmatrix address parts
    const uint32_t klane = ((lane & 7) * RSTRIDE) * 4 + (lane >> 3) * 16;
    // V trans: rows = s (k-dim), matrices: {k0 d0, k8 d0, k0 d8, k8 d8}
    const uint32_t vlane = (((lane & 7) + ((lane >> 3) & 1) * 8) * RSTRIDE) * 4
                         + (lane >> 4) * 16;

    float Oc[2][8][4];
    #pragma unroll
    for (int mf = 0; mf < 2; ++mf)
        #pragma unroll
        for (int nf = 0; nf < 8; ++nf)
            #pragma unroll
            for (int i = 0; i < 4; ++i) Oc[mf][nf][i] = 0.0f;
    float ls[2][2] = {{0.f, 0.f}, {0.f, 0.f}};

    float4 kpre[4], vpre[4];
    for (int it = 0; it < NSTEPS; ++it) {
        // ---- prefetch next K/V tile into registers (latency hidden by compute) ----
        if (it + 1 < NSTEPS) {
            const int s0n = (it + 1) * S_TILE;
            #pragma unroll
            for (int j = 0; j < 4; ++j) {
                const int idx = tid + j * THREADS;
                const int r   = idx >> 4;
                const int c4  = (idx & 15) << 2;
                kpre[j] = *reinterpret_cast<const float4*>(Kh + (s0n + r) * 512 + c4);
                vpre[j] = *reinterpret_cast<const float4*>(Vh + (s0n + r) * 512 + c4);
            }
        }

        const uint32_t bufb  = (uint32_t)(it & 1) * (BUF_WORDS * 4);
        const uint32_t kaddr = sbase + bufb + klane;
        const uint32_t vaddr = sbase + bufb + KV_WORDS * 4 + vlane;

        // ---- compute: QK + exp2 + PV, K/V frags shared across both mf blocks ----
        uint32_t Pa[2][2][4];
        #pragma unroll
        for (int nf = 0; nf < 4; ++nf) {     // 4 n-blocks of 8 score cols
            uint32_t Kf[8];
            const uint32_t ka = kaddr + (uint32_t)nf * (8 * RSTRIDE * 4);
            ldm_x4(Kf, ka);
            ldm_x4(Kf + 4, ka + 64);
            // Split accumulators: 8 independent MMA chains instead of 2 chains
            // of 4 (fp accumulation reassociated manually; ptxas can't).
            float C0a[4] = {0.f, 0.f, 0.f, 0.f};
            float C0b[4] = {0.f, 0.f, 0.f, 0.f};
            float C1a[4] = {0.f, 0.f, 0.f, 0.f};
            float C1b[4] = {0.f, 0.f, 0.f, 0.f};
            mma_f16(C0a, Qa[0][0], Kf[0], Kf[1]);
            mma_f16(C1a, Qa[1][0], Kf[0], Kf[1]);
            mma_f16(C0b, Qa[0][1], Kf[2], Kf[3]);
            mma_f16(C1b, Qa[1][1], Kf[2], Kf[3]);
            mma_f16(C0a, Qa[0][2], Kf[4], Kf[5]);
            mma_f16(C1a, Qa[1][2], Kf[4], Kf[5]);
            mma_f16(C0b, Qa[0][3], Kf[6], Kf[7]);
            mma_f16(C1b, Qa[1][3], Kf[6], Kf[7]);

            const float a0 = pexp2(C0a[0] + C0b[0]), a1 = pexp2(C0a[1] + C0b[1]);
            const float a2 = pexp2(C0a[2] + C0b[2]), a3 = pexp2(C0a[3] + C0b[3]);
            const float b0 = pexp2(C1a[0] + C1b[0]), b1 = pexp2(C1a[1] + C1b[1]);
            const float b2 = pexp2(C1a[2] + C1b[2]), b3 = pexp2(C1a[3] + C1b[3]);
            ls[0][0] += a0 + a1;  ls[0][1] += a2 + a3;
            ls[1][0] += b0 + b1;  ls[1][1] += b2 + b3;
            const int kcp = nf >> 1;
            if ((nf & 1) == 0) {
                Pa[0][kcp][0] = pack_h2(a0, a1);
                Pa[0][kcp][1] = pack_h2(a2, a3);
                Pa[1][kcp][0] = pack_h2(b0, b1);
                Pa[1][kcp][1] = pack_h2(b2, b3);
            } else {
                Pa[0][kcp][2] = pack_h2(a0, a1);
                Pa[0][kcp][3] = pack_h2(a2, a3);
                Pa[1][kcp][2] = pack_h2(b0, b1);
                Pa[1][kcp][3] = pack_h2(b2, b3);
                // Pa[*][kcp] complete -> PV for this k-chunk, V frags shared by mf
                #pragma unroll
                for (int nv = 0; nv < 8; nv += 2) {
                    uint32_t Vf[4];
                    ldm_x4_t(Vf, vaddr + (uint32_t)kcp * (16 * RSTRIDE * 4)
                                 + (uint32_t)nv * 16);
                    mma_f16(Oc[0][nv],     Pa[0][kcp], Vf[0], Vf[1]);
                    mma_f16(Oc[0][nv + 1], Pa[0][kcp], Vf[2], Vf[3]);
                    mma_f16(Oc[1][nv],     Pa[1][kcp], Vf[0], Vf[1]);
                    mma_f16(Oc[1][nv + 1], Pa[1][kcp], Vf[2], Vf[3]);
                }
            }
        }

        // ---- store prefetched tile into the other buffer, then barrier ----
        if (it + 1 < NSTEPS) {
            const uint32_t ob = ((it + 1) & 1) * BUF_WORDS;
            #pragma unroll
            for (int j = 0; j < 4; ++j) {
                const int idx = tid + j * THREADS;
                const int r   = idx >> 4;
                const int c4  = (idx & 15) << 2;
                *reinterpret_cast<uint2*>(&sm[ob + r * RSTRIDE + (c4 >> 1)])
                    = make_uint2(pack_h2(kpre[j].x, kpre[j].y),
                                 pack_h2(kpre[j].z, kpre[j].w));
                *reinterpret_cast<uint2*>(&sm[ob + KV_WORDS + r * RSTRIDE + (c4 >> 1)])
                    = make_uint2(pack_h2(vpre[j].x, vpre[j].y),
                                 pack_h2(vpre[j].z, vpre[j].w));
            }
            __syncthreads();
        }
    }

    // ---- Epilogue: per-row lsum (quad reduce), normalize, store ----
    #pragma unroll
    for (int mf = 0; mf < 2; ++mf) {
        float v0 = ls[mf][0], v1 = ls[mf][1];
        v0 += __shfl_xor_sync(0xffffffffu, v0, 1);
        v0 += __shfl_xor_sync(0xffffffffu, v0, 2);
        v1 += __shfl_xor_sync(0xffffffffu, v1, 1);
        v1 += __shfl_xor_sync(0xffffffffu, v1, 2);
        const float inv0 = 1.0f / v0;
        const float inv1 = 1.0f / v1;

        const int r0 = w * 32 + mf * 16 + g;
        float* o0 = Og + bn * (L_ * H_ * D_) + (l0 + r0) * 512 + h * 64;
        float* o1 = o0 + 8 * 512;
        #pragma unroll
        for (int nf = 0; nf < 8; ++nf) {
            *reinterpret_cast<float2*>(o0 + nf * 8 + 2 * t)
                = make_float2(Oc[mf][nf][0] * inv0, Oc[mf][nf][1] * inv0);
            *reinterpret_cast<float2*>(o1 + nf * 8 + 2 * t)
                = make_float2(Oc[mf][nf][2] * inv1, Oc[mf][nf][3] * inv1);
        }
    }
}

extern "C" void kernel_launch(void* const* d_in, const int* in_sizes, int n_in,
                              void* d_out, int out_size) {
    const float* Q = (const float*)d_in[0];
    const float* K = (const float*)d_in[1];
    const float* V = (const float*)d_in[2];
    float* O = (float*)d_out;

    cudaFuncSetAttribute(attn_hmma_f16_kernel,
                         cudaFuncAttributeMaxDynamicSharedMemorySize, SMEM_BYTES);

    dim3 grid(L_ / M_TILE, B_ * N_ * H_);   // (4, 224) = 896 CTAs
    attn_hmma_f16_kernel<<<grid, THREADS, SMEM_BYTES>>>(Q, K, V, O);
}